// round 9
// baseline (speedup 1.0000x reference)
#include <cuda_runtime.h>
#include <cuda_fp16.h>
#include <cstdint>

// Problem constants
#define K_DIM 4096
#define N_DIM 4096
#define M_DIM 8192

// GEMM tiling: CTA 256x128x64, 8 warps of 64x64 (4m x 2n)
#define BM 256
#define BN 128
#define BK 64
#define STAGES 3
#define THREADS 256

// smem layout
#define ROWB 144                     // 64 halves (128B) + 16B pad -> conflict-free ldsm
#define ARR_A (256 * ROWB)           // 36864 B (A tile)
#define ARR_W (128 * ROWB)           // 18432 B (B tile)
#define STG_B (ARR_A + ARR_W)        // 55296 B per stage
#define SMEM_TOTAL (STAGES * STG_B)  // 165888 B -> 1 CTA/SM, 8 warps

// Scratch: fp16 operands. Scale folded into w at prep (adds ~2^-11 w error).
__device__ __half g_xh[(long)M_DIM * K_DIM];
__device__ __half g_wh[(long)N_DIM * K_DIM];

// ---------------------------------------------------------------------------
// Prep kernels
// ---------------------------------------------------------------------------
__global__ void k_prep_x(const float* __restrict__ x, long n4) {
    long i = (long)blockIdx.x * blockDim.x + threadIdx.x;
    if (i >= n4) return;
    float4 v = reinterpret_cast<const float4*>(x)[i];
    __half2* hi2 = reinterpret_cast<__half2*>(g_xh);
    hi2[2 * i]     = __halves2half2(__float2half_rn(v.x), __float2half_rn(v.y));
    hi2[2 * i + 1] = __halves2half2(__float2half_rn(v.z), __float2half_rn(v.w));
}

__global__ void k_prep_w(const float* __restrict__ wq,
                         const float* __restrict__ scales, long n4) {
    long i = (long)blockIdx.x * blockDim.x + threadIdx.x;
    if (i >= n4) return;
    const float s = scales[(4 * i) >> 7];   // 128-elem blocks; float4 never straddles
    float4 v = reinterpret_cast<const float4*>(wq)[i];
    __half2* w2 = reinterpret_cast<__half2*>(g_wh);
    w2[2 * i]     = __halves2half2(__float2half_rn(v.x * s), __float2half_rn(v.y * s));
    w2[2 * i + 1] = __halves2half2(__float2half_rn(v.z * s), __float2half_rn(v.w * s));
}

// ---------------------------------------------------------------------------
// MMA helpers
// ---------------------------------------------------------------------------
__device__ __forceinline__ void cp16(uint32_t saddr, const void* g) {
    asm volatile("cp.async.cg.shared.global [%0], [%1], 16;" ::"r"(saddr), "l"(g));
}
__device__ __forceinline__ void ldsm4(uint32_t* r, uint32_t addr) {
    asm volatile("ldmatrix.sync.aligned.m8n8.x4.shared.b16 {%0,%1,%2,%3}, [%4];"
                 : "=r"(r[0]), "=r"(r[1]), "=r"(r[2]), "=r"(r[3]) : "r"(addr));
}
__device__ __forceinline__ void mma_f16(float* c, const uint32_t* a, const uint32_t* b) {
    asm volatile(
        "mma.sync.aligned.m16n8k16.row.col.f32.f16.f16.f32 "
        "{%0,%1,%2,%3}, {%4,%5,%6,%7}, {%8,%9}, {%0,%1,%2,%3};"
        : "+f"(c[0]), "+f"(c[1]), "+f"(c[2]), "+f"(c[3])
        : "r"(a[0]), "r"(a[1]), "r"(a[2]), "r"(a[3]), "r"(b[0]), "r"(b[1]));
}

// ---------------------------------------------------------------------------
// GEMM: out[M,N] = X16 @ W16^T + bias   (scales pre-folded into W16)
// ---------------------------------------------------------------------------
__global__ __launch_bounds__(THREADS, 1)
void k_gemm(const float* __restrict__ bias, float* __restrict__ out) {
    extern __shared__ char smc[];
    const uint32_t sbase = (uint32_t)__cvta_generic_to_shared(smc);
    const int tid  = threadIdx.x;
    const int lane = tid & 31;
    const int warp = tid >> 5;
    const long m0 = (long)blockIdx.y * BM;
    const long n0 = (long)blockIdx.x * BN;
    const int wm = (warp & 3) * 64;    // 4 m-slots
    const int wn = (warp >> 2) * 64;   // 2 n-slots

    float c[4][8][4];
#pragma unroll
    for (int mi = 0; mi < 4; ++mi)
#pragma unroll
        for (int ni = 0; ni < 8; ++ni)
#pragma unroll
            for (int j = 0; j < 4; ++j) c[mi][ni][j] = 0.f;

    // cp.async loader: A 2048 chunks (8/thr), W 1024 chunks (4/thr)
    auto load_stage = [&](int kt, int s) {
        const uint32_t st = sbase + s * STG_B;
        const int kc0 = kt * BK;
#pragma unroll
        for (int i = 0; i < 8; ++i) {
            const int cch = tid + i * THREADS;
            const int row = cch >> 3;
            const int ch  = cch & 7;
            cp16(st + (uint32_t)(row * ROWB + ch * 16),
                 g_xh + (m0 + row) * K_DIM + kc0 + ch * 8);
        }
#pragma unroll
        for (int i = 0; i < 4; ++i) {
            const int cch = tid + i * THREADS;
            const int row = cch >> 3;
            const int ch  = cch & 7;
            cp16(st + ARR_A + (uint32_t)(row * ROWB + ch * 16),
                 g_wh + (n0 + row) * (long)K_DIM + kc0 + ch * 8);
        }
        asm volatile("cp.async.commit_group;");
    };

    const int KT = K_DIM / BK;   // 64
    load_stage(0, 0);
    load_stage(1, 1);

    const uint32_t a_rowoff = (uint32_t)(wm + (lane & 15));
    const uint32_t a_cb     = (uint32_t)((lane >> 4) * 16);
    const uint32_t b_rowoff = (uint32_t)(wn + (lane & 7) + ((lane >> 4) * 8));
    const uint32_t b_cb     = (uint32_t)(((lane >> 3) & 1) * 16);

    uint32_t ah[2][4][4], bq[2][4][4];

    auto load_frags = [&](uint32_t st, int kk, int buf) {
#pragma unroll
        for (int mi = 0; mi < 4; ++mi)
            ldsm4(ah[buf][mi], st + (a_rowoff + mi * 16) * ROWB + kk * 32 + a_cb);
#pragma unroll
        for (int nj = 0; nj < 4; ++nj)
            ldsm4(bq[buf][nj], st + ARR_A + (b_rowoff + nj * 16) * ROWB + kk * 32 + b_cb);
    };
    auto do_mmas = [&](int buf) {
#pragma unroll
        for (int mi = 0; mi < 4; ++mi)
#pragma unroll
            for (int nj = 0; nj < 4; ++nj) {
                mma_f16(c[mi][2 * nj],     ah[buf][mi], &bq[buf][nj][0]);
                mma_f16(c[mi][2 * nj + 1], ah[buf][mi], &bq[buf][nj][2]);
            }
    };

    for (int kt = 0; kt < KT; ++kt) {
        const int s = kt % STAGES;
        asm volatile("cp.async.wait_group %0;" :: "n"(STAGES - 2));
        __syncthreads();
        if (kt + 2 < KT) load_stage(kt + 2, (kt + 2) % STAGES);

        const uint32_t st = sbase + s * STG_B;
        load_frags(st, 0, 0);
#pragma unroll
        for (int kk = 0; kk < 4; ++kk) {
            if (kk < 3) load_frags(st, kk + 1, (kk + 1) & 1);
            do_mmas(kk & 1);
        }
    }

    // Epilogue: y += bias, store (each warp: 64 rows x 64 cols)
    const int qr = lane >> 2;
    const int qc = (lane & 3) * 2;
#pragma unroll
    for (int mi = 0; mi < 4; ++mi) {
        const long gm = m0 + wm + mi * 16 + qr;
        float* o0 = out + gm * N_DIM + n0 + wn;
        float* o1 = o0 + 8L * N_DIM;
#pragma unroll
        for (int ni = 0; ni < 8; ++ni) {
            const int col = (int)n0 + wn + ni * 8 + qc;
            const float b0 = __ldg(bias + col);
            const float b1 = __ldg(bias + col + 1);
            float2 v0 = make_float2(c[mi][ni][0] + b0, c[mi][ni][1] + b1);
            float2 v1 = make_float2(c[mi][ni][2] + b0, c[mi][ni][3] + b1);
            *reinterpret_cast<float2*>(o0 + ni * 8 + qc) = v0;
            *reinterpret_cast<float2*>(o1 + ni * 8 + qc) = v1;
        }
    }
}

// ---------------------------------------------------------------------------
// Launch
// ---------------------------------------------------------------------------
extern "C" void kernel_launch(void* const* d_in, const int* in_sizes, int n_in,
                              void* d_out, int out_size) {
    const float* x      = (const float*)d_in[0];
    const float* wq     = (const float*)d_in[1];
    const float* scales = (const float*)d_in[2];
    const float* bias   = (const float*)d_in[3];
    float* out = (float*)d_out;

    const long n_x = in_sizes[0];           // M*K
    const long M   = n_x / K_DIM;           // 8192
    const long n_w = (long)N_DIM * K_DIM;

    {
        long n4 = n_x / 4;
        k_prep_x<<<(int)((n4 + 255) / 256), 256>>>(x, n4);
    }
    {
        long n4 = n_w / 4;
        k_prep_w<<<(int)((n4 + 255) / 256), 256>>>(wq, scales, n4);
    }

    cudaFuncSetAttribute(k_gemm, cudaFuncAttributeMaxDynamicSharedMemorySize,
                         SMEM_TOTAL);
    dim3 grid(N_DIM / BN, (unsigned)(M / BM));
    k_gemm<<<grid, THREADS, SMEM_TOTAL>>>(bias, out);
}

// round 10
// speedup vs baseline: 1.0633x; 1.0633x over previous
#include <cuda_runtime.h>
#include <cuda_fp16.h>
#include <cstdint>

// Problem constants
#define K_DIM 4096
#define N_DIM 4096
#define M_DIM 8192

// GEMM tiling: CTA 128x128x64, 4 warps of 64x64 (2m x 2n), 2 CTAs/SM
#define BM 128
#define BN 128
#define BK 64
#define STAGES 3
#define THREADS 128

// smem layout
#define ROWB 144                    // 64 halves (128B) + 16B pad -> conflict-free ldsm
#define ARR_B (128 * ROWB)          // 18432 B per operand tile
#define STG_B (2 * ARR_B)           // x, w tiles per stage
#define SMEM_TOTAL (STAGES * STG_B) // 110592 B -> 2 CTAs/SM

// Scratch: fp16 operands. Scale folded into w at prep (adds ~2^-11 w error).
__device__ __half g_xh[(long)M_DIM * K_DIM];
__device__ __half g_wh[(long)N_DIM * K_DIM];

// ---------------------------------------------------------------------------
// Prep kernels
// ---------------------------------------------------------------------------
__global__ void k_prep_x(const float* __restrict__ x, long n4) {
    long i = (long)blockIdx.x * blockDim.x + threadIdx.x;
    if (i >= n4) return;
    float4 v = reinterpret_cast<const float4*>(x)[i];
    __half2* hi2 = reinterpret_cast<__half2*>(g_xh);
    hi2[2 * i]     = __halves2half2(__float2half_rn(v.x), __float2half_rn(v.y));
    hi2[2 * i + 1] = __halves2half2(__float2half_rn(v.z), __float2half_rn(v.w));
}

__global__ void k_prep_w(const float* __restrict__ wq,
                         const float* __restrict__ scales, long n4) {
    long i = (long)blockIdx.x * blockDim.x + threadIdx.x;
    if (i >= n4) return;
    const float s = scales[(4 * i) >> 7];   // 128-elem blocks; float4 never straddles
    float4 v = reinterpret_cast<const float4*>(wq)[i];
    __half2* w2 = reinterpret_cast<__half2*>(g_wh);
    w2[2 * i]     = __halves2half2(__float2half_rn(v.x * s), __float2half_rn(v.y * s));
    w2[2 * i + 1] = __halves2half2(__float2half_rn(v.z * s), __float2half_rn(v.w * s));
}

// ---------------------------------------------------------------------------
// MMA helpers
// ---------------------------------------------------------------------------
__device__ __forceinline__ void cp16(uint32_t saddr, const void* g) {
    asm volatile("cp.async.cg.shared.global [%0], [%1], 16;" ::"r"(saddr), "l"(g));
}
__device__ __forceinline__ void ldsm4(uint32_t* r, uint32_t addr) {
    asm volatile("ldmatrix.sync.aligned.m8n8.x4.shared.b16 {%0,%1,%2,%3}, [%4];"
                 : "=r"(r[0]), "=r"(r[1]), "=r"(r[2]), "=r"(r[3]) : "r"(addr));
}
__device__ __forceinline__ void mma_f16(float* c, const uint32_t* a, const uint32_t* b) {
    asm volatile(
        "mma.sync.aligned.m16n8k16.row.col.f32.f16.f16.f32 "
        "{%0,%1,%2,%3}, {%4,%5,%6,%7}, {%8,%9}, {%0,%1,%2,%3};"
        : "+f"(c[0]), "+f"(c[1]), "+f"(c[2]), "+f"(c[3])
        : "r"(a[0]), "r"(a[1]), "r"(a[2]), "r"(a[3]), "r"(b[0]), "r"(b[1]));
}

// ---------------------------------------------------------------------------
// GEMM: out[M,N] = X16 @ W16^T + bias   (scales pre-folded into W16)
// 4 warps, each 64x64, register fragment double-buffering.
// ---------------------------------------------------------------------------
__global__ __launch_bounds__(THREADS, 2)
void k_gemm(const float* __restrict__ bias, float* __restrict__ out) {
    extern __shared__ char smc[];
    const uint32_t sbase = (uint32_t)__cvta_generic_to_shared(smc);
    const int tid  = threadIdx.x;
    const int lane = tid & 31;
    const int warp = tid >> 5;
    const long m0 = (long)blockIdx.y * BM;
    const long n0 = (long)blockIdx.x * BN;
    const int wm = (warp & 1) * 64;
    const int wn = (warp >> 1) * 64;

    float c[4][8][4];
#pragma unroll
    for (int mi = 0; mi < 4; ++mi)
#pragma unroll
        for (int ni = 0; ni < 8; ++ni)
#pragma unroll
            for (int j = 0; j < 4; ++j) c[mi][ni][j] = 0.f;

    // cp.async loader: 2048 16B-chunks per stage (2 arrays x 1024), 16/thread
    auto load_stage = [&](int kt, int s) {
        const uint32_t st = sbase + s * STG_B;
        const int kc0 = kt * BK;
#pragma unroll
        for (int i = 0; i < 8; ++i) {
            const int cch = tid + i * THREADS;
            const int row = cch >> 3;
            const int ch  = cch & 7;
            const uint32_t off = (uint32_t)(row * ROWB + ch * 16);
            cp16(st + off,         g_xh + (m0 + row) * K_DIM + kc0 + ch * 8);
            cp16(st + ARR_B + off, g_wh + (n0 + row) * (long)K_DIM + kc0 + ch * 8);
        }
        asm volatile("cp.async.commit_group;");
    };

    const int KT = K_DIM / BK;   // 64
    load_stage(0, 0);
    load_stage(1, 1);

    const uint32_t a_rowoff = (uint32_t)(wm + (lane & 15));
    const uint32_t a_cb     = (uint32_t)((lane >> 4) * 16);
    const uint32_t b_rowoff = (uint32_t)(wn + (lane & 7) + ((lane >> 4) * 8));
    const uint32_t b_cb     = (uint32_t)(((lane >> 3) & 1) * 16);

    uint32_t ah[2][4][4], bq[2][4][4];

    auto load_frags = [&](uint32_t st, int kk, int buf) {
#pragma unroll
        for (int mi = 0; mi < 4; ++mi)
            ldsm4(ah[buf][mi], st + (a_rowoff + mi * 16) * ROWB + kk * 32 + a_cb);
#pragma unroll
        for (int nj = 0; nj < 4; ++nj)
            ldsm4(bq[buf][nj], st + ARR_B + (b_rowoff + nj * 16) * ROWB + kk * 32 + b_cb);
    };
    auto do_mmas = [&](int buf) {
#pragma unroll
        for (int mi = 0; mi < 4; ++mi)
#pragma unroll
            for (int nj = 0; nj < 4; ++nj) {
                mma_f16(c[mi][2 * nj],     ah[buf][mi], &bq[buf][nj][0]);
                mma_f16(c[mi][2 * nj + 1], ah[buf][mi], &bq[buf][nj][2]);
            }
    };

    for (int kt = 0; kt < KT; ++kt) {
        const int s = kt % STAGES;
        asm volatile("cp.async.wait_group %0;" :: "n"(STAGES - 2));
        __syncthreads();
        if (kt + 2 < KT) load_stage(kt + 2, (kt + 2) % STAGES);

        const uint32_t st = sbase + s * STG_B;
        load_frags(st, 0, 0);
#pragma unroll
        for (int kk = 0; kk < 4; ++kk) {
            if (kk < 3) load_frags(st, kk + 1, (kk + 1) & 1);
            do_mmas(kk & 1);
        }
    }

    // Epilogue: y += bias, store (each warp: 64 rows x 64 cols)
    const int qr = lane >> 2;
    const int qc = (lane & 3) * 2;
#pragma unroll
    for (int mi = 0; mi < 4; ++mi) {
        const long gm = m0 + wm + mi * 16 + qr;
        float* o0 = out + gm * N_DIM + n0 + wn;
        float* o1 = o0 + 8L * N_DIM;
#pragma unroll
        for (int ni = 0; ni < 8; ++ni) {
            const int col = (int)n0 + wn + ni * 8 + qc;
            const float b0 = __ldg(bias + col);
            const float b1 = __ldg(bias + col + 1);
            float2 v0 = make_float2(c[mi][ni][0] + b0, c[mi][ni][1] + b1);
            float2 v1 = make_float2(c[mi][ni][2] + b0, c[mi][ni][3] + b1);
            *reinterpret_cast<float2*>(o0 + ni * 8 + qc) = v0;
            *reinterpret_cast<float2*>(o1 + ni * 8 + qc) = v1;
        }
    }
}

// ---------------------------------------------------------------------------
// Launch
// ---------------------------------------------------------------------------
extern "C" void kernel_launch(void* const* d_in, const int* in_sizes, int n_in,
                              void* d_out, int out_size) {
    const float* x      = (const float*)d_in[0];
    const float* wq     = (const float*)d_in[1];
    const float* scales = (const float*)d_in[2];
    const float* bias   = (const float*)d_in[3];
    float* out = (float*)d_out;

    const long n_x = in_sizes[0];           // M*K
    const long M   = n_x / K_DIM;           // 8192
    const long n_w = (long)N_DIM * K_DIM;

    {
        long n4 = n_x / 4;
        k_prep_x<<<(int)((n4 + 255) / 256), 256>>>(x, n4);
    }
    {
        long n4 = n_w / 4;
        k_prep_w<<<(int)((n4 + 255) / 256), 256>>>(wq, scales, n4);
    }

    cudaFuncSetAttribute(k_gemm, cudaFuncAttributeMaxDynamicSharedMemorySize,
                         SMEM_TOTAL);
    dim3 grid(N_DIM / BN, (unsigned)(M / BM));
    k_gemm<<<grid, THREADS, SMEM_TOTAL>>>(bias, out);
}

// round 13
// speedup vs baseline: 1.0645x; 1.0011x over previous
#include <cuda_runtime.h>
#include <cuda_fp16.h>
#include <cstdint>

// Problem constants
#define K_DIM 4096
#define N_DIM 4096
#define M_DIM 8192

// GEMM tiling: CTA 128x128x64, 4 warps of 64x64 (2m x 2n), 2 CTAs/SM
#define BM 128
#define BN 128
#define BK 64
#define STAGES 3
#define THREADS 128

// smem layout
#define ROWB 144                    // 64 halves (128B) + 16B pad -> conflict-free ldsm
#define ARR_B (128 * ROWB)          // 18432 B per operand tile
#define STG_B (2 * ARR_B)           // x, w tiles per stage
#define SMEM_TOTAL (STAGES * STG_B) // 110592 B -> 2 CTAs/SM

// Scratch: fp16 operands. Scale folded into w at prep (adds ~2^-11 w error).
__device__ __half g_xh[(long)M_DIM * K_DIM];
__device__ __half g_wh[(long)N_DIM * K_DIM];

// ---------------------------------------------------------------------------
// Fused prep kernel: converts x -> fp16 and w*scale -> fp16 in one launch.
// Index space is float4 units: [0, n4x) -> x, [n4x, n4x + n4w) -> w.
// ---------------------------------------------------------------------------
__global__ void k_prep(const float* __restrict__ x, const float* __restrict__ wq,
                       const float* __restrict__ scales, long n4x, long n4w) {
    long i = (long)blockIdx.x * blockDim.x + threadIdx.x;
    if (i < n4x) {
        float4 v = reinterpret_cast<const float4*>(x)[i];
        __half2* hi2 = reinterpret_cast<__half2*>(g_xh);
        hi2[2 * i]     = __halves2half2(__float2half_rn(v.x), __float2half_rn(v.y));
        hi2[2 * i + 1] = __halves2half2(__float2half_rn(v.z), __float2half_rn(v.w));
    } else {
        long j = i - n4x;
        if (j >= n4w) return;
        const float s = scales[(4 * j) >> 7];   // 128-elem blocks; float4 never straddles
        float4 v = reinterpret_cast<const float4*>(wq)[j];
        __half2* w2 = reinterpret_cast<__half2*>(g_wh);
        w2[2 * j]     = __halves2half2(__float2half_rn(v.x * s), __float2half_rn(v.y * s));
        w2[2 * j + 1] = __halves2half2(__float2half_rn(v.z * s), __float2half_rn(v.w * s));
    }
}

// ---------------------------------------------------------------------------
// MMA helpers
// ---------------------------------------------------------------------------
__device__ __forceinline__ void cp16(uint32_t saddr, const void* g) {
    asm volatile("cp.async.cg.shared.global [%0], [%1], 16;" ::"r"(saddr), "l"(g));
}
__device__ __forceinline__ void ldsm4(uint32_t* r, uint32_t addr) {
    asm volatile("ldmatrix.sync.aligned.m8n8.x4.shared.b16 {%0,%1,%2,%3}, [%4];"
                 : "=r"(r[0]), "=r"(r[1]), "=r"(r[2]), "=r"(r[3]) : "r"(addr));
}
__device__ __forceinline__ void mma_f16(float* c, const uint32_t* a, const uint32_t* b) {
    asm volatile(
        "mma.sync.aligned.m16n8k16.row.col.f32.f16.f16.f32 "
        "{%0,%1,%2,%3}, {%4,%5,%6,%7}, {%8,%9}, {%0,%1,%2,%3};"
        : "+f"(c[0]), "+f"(c[1]), "+f"(c[2]), "+f"(c[3])
        : "r"(a[0]), "r"(a[1]), "r"(a[2]), "r"(a[3]), "r"(b[0]), "r"(b[1]));
}

// ---------------------------------------------------------------------------
// GEMM: out[M,N] = X16 @ W16^T + bias   (scales pre-folded into W16)
// 4 warps, each 64x64, register fragment double-buffering. (R9 champion)
// ---------------------------------------------------------------------------
__global__ __launch_bounds__(THREADS, 2)
void k_gemm(const float* __restrict__ bias, float* __restrict__ out) {
    extern __shared__ char smc[];
    const uint32_t sbase = (uint32_t)__cvta_generic_to_shared(smc);
    const int tid  = threadIdx.x;
    const int lane = tid & 31;
    const int warp = tid >> 5;
    const long m0 = (long)blockIdx.y * BM;
    const long n0 = (long)blockIdx.x * BN;
    const int wm = (warp & 1) * 64;
    const int wn = (warp >> 1) * 64;

    float c[4][8][4];
#pragma unroll
    for (int mi = 0; mi < 4; ++mi)
#pragma unroll
        for (int ni = 0; ni < 8; ++ni)
#pragma unroll
            for (int j = 0; j < 4; ++j) c[mi][ni][j] = 0.f;

    // cp.async loader: 2048 16B-chunks per stage (2 arrays x 1024), 16/thread
    auto load_stage = [&](int kt, int s) {
        const uint32_t st = sbase + s * STG_B;
        const int kc0 = kt * BK;
#pragma unroll
        for (int i = 0; i < 8; ++i) {
            const int cch = tid + i * THREADS;
            const int row = cch >> 3;
            const int ch  = cch & 7;
            const uint32_t off = (uint32_t)(row * ROWB + ch * 16);
            cp16(st + off,         g_xh + (m0 + row) * K_DIM + kc0 + ch * 8);
            cp16(st + ARR_B + off, g_wh + (n0 + row) * (long)K_DIM + kc0 + ch * 8);
        }
        asm volatile("cp.async.commit_group;");
    };

    const int KT = K_DIM / BK;   // 64
    load_stage(0, 0);
    load_stage(1, 1);

    const uint32_t a_rowoff = (uint32_t)(wm + (lane & 15));
    const uint32_t a_cb     = (uint32_t)((lane >> 4) * 16);
    const uint32_t b_rowoff = (uint32_t)(wn + (lane & 7) + ((lane >> 4) * 8));
    const uint32_t b_cb     = (uint32_t)(((lane >> 3) & 1) * 16);

    uint32_t ah[2][4][4], bq[2][4][4];

    auto load_frags = [&](uint32_t st, int kk, int buf) {
#pragma unroll
        for (int mi = 0; mi < 4; ++mi)
            ldsm4(ah[buf][mi], st + (a_rowoff + mi * 16) * ROWB + kk * 32 + a_cb);
#pragma unroll
        for (int nj = 0; nj < 4; ++nj)
            ldsm4(bq[buf][nj], st + ARR_B + (b_rowoff + nj * 16) * ROWB + kk * 32 + b_cb);
    };
    auto do_mmas = [&](int buf) {
#pragma unroll
        for (int mi = 0; mi < 4; ++mi)
#pragma unroll
            for (int nj = 0; nj < 4; ++nj) {
                mma_f16(c[mi][2 * nj],     ah[buf][mi], &bq[buf][nj][0]);
                mma_f16(c[mi][2 * nj + 1], ah[buf][mi], &bq[buf][nj][2]);
            }
    };

    for (int kt = 0; kt < KT; ++kt) {
        const int s = kt % STAGES;
        asm volatile("cp.async.wait_group %0;" :: "n"(STAGES - 2));
        __syncthreads();
        if (kt + 2 < KT) load_stage(kt + 2, (kt + 2) % STAGES);

        const uint32_t st = sbase + s * STG_B;
        load_frags(st, 0, 0);
#pragma unroll
        for (int kk = 0; kk < 4; ++kk) {
            if (kk < 3) load_frags(st, kk + 1, (kk + 1) & 1);
            do_mmas(kk & 1);
        }
    }

    // Epilogue: y += bias, store (each warp: 64 rows x 64 cols)
    const int qr = lane >> 2;
    const int qc = (lane & 3) * 2;
#pragma unroll
    for (int mi = 0; mi < 4; ++mi) {
        const long gm = m0 + wm + mi * 16 + qr;
        float* o0 = out + gm * N_DIM + n0 + wn;
        float* o1 = o0 + 8L * N_DIM;
#pragma unroll
        for (int ni = 0; ni < 8; ++ni) {
            const int col = (int)n0 + wn + ni * 8 + qc;
            const float b0 = __ldg(bias + col);
            const float b1 = __ldg(bias + col + 1);
            float2 v0 = make_float2(c[mi][ni][0] + b0, c[mi][ni][1] + b1);
            float2 v1 = make_float2(c[mi][ni][2] + b0, c[mi][ni][3] + b1);
            *reinterpret_cast<float2*>(o0 + ni * 8 + qc) = v0;
            *reinterpret_cast<float2*>(o1 + ni * 8 + qc) = v1;
        }
    }
}

// ---------------------------------------------------------------------------
// Launch
// ---------------------------------------------------------------------------
extern "C" void kernel_launch(void* const* d_in, const int* in_sizes, int n_in,
                              void* d_out, int out_size) {
    const float* x      = (const float*)d_in[0];
    const float* wq     = (const float*)d_in[1];
    const float* scales = (const float*)d_in[2];
    const float* bias   = (const float*)d_in[3];
    float* out = (float*)d_out;

    const long n_x = in_sizes[0];           // M*K
    const long M   = n_x / K_DIM;           // 8192
    const long n_w = (long)N_DIM * K_DIM;

    const long n4x = n_x / 4;
    const long n4w = n_w / 4;
    const long n4  = n4x + n4w;
    k_prep<<<(int)((n4 + 255) / 256), 256>>>(x, wq, scales, n4x, n4w);

    cudaFuncSetAttribute(k_gemm, cudaFuncAttributeMaxDynamicSharedMemorySize,
                         SMEM_TOTAL);
    dim3 grid(N_DIM / BN, (unsigned)(M / BM));
    k_gemm<<<grid, THREADS, SMEM_TOTAL>>>(bias, out);
}

// round 17
// speedup vs baseline: 1.0748x; 1.0097x over previous
#include <cuda_runtime.h>
#include <cuda_fp16.h>
#include <cstdint>

// Problem constants
#define K_DIM 4096
#define N_DIM 4096
#define M_DIM 8192

// GEMM tiling: CTA 128x128x64, 4 warps of 64x64 (2m x 2n), 2 CTAs/SM
#define BM 128
#define BN 128
#define BK 64
#define STAGES 3
#define THREADS 128

// smem layout
#define ROWB 144                    // 64 halves (128B) + 16B pad -> conflict-free ldsm
#define ARR_B (128 * ROWB)          // 18432 B per operand tile
#define STG_B (2 * ARR_B)           // x, w tiles per stage
#define SMEM_TOTAL (STAGES * STG_B) // 110592 B -> 2 CTAs/SM

// Scratch: fp16 operands. Scale folded into w at prep (adds ~2^-11 w error).
__device__ __half g_xh[(long)M_DIM * K_DIM];
__device__ __half g_wh[(long)N_DIM * K_DIM];

// ---------------------------------------------------------------------------
// Fused prep kernel, 8 floats/thread: x -> fp16, w*scale -> fp16.
// Index space is 8-float units: [0, n8x) -> x, [n8x, n8x + n8w) -> w.
// Two adjacent LDG.128 per thread (MLP=2), one STG.128 out.
// ---------------------------------------------------------------------------
__device__ __forceinline__ uint32_t pack2(float a, float b) {
    __half2 h = __halves2half2(__float2half_rn(a), __float2half_rn(b));
    return *reinterpret_cast<uint32_t*>(&h);
}

__global__ __launch_bounds__(256)
void k_prep(const float* __restrict__ x, const float* __restrict__ wq,
            const float* __restrict__ scales, long n8x, long n8w) {
    long i = (long)blockIdx.x * blockDim.x + threadIdx.x;
    if (i < n8x) {
        const float4* p = reinterpret_cast<const float4*>(x) + 2 * i;
        float4 a = p[0];
        float4 b = p[1];
        uint4 o;
        o.x = pack2(a.x, a.y); o.y = pack2(a.z, a.w);
        o.z = pack2(b.x, b.y); o.w = pack2(b.z, b.w);
        reinterpret_cast<uint4*>(g_xh)[i] = o;
    } else {
        long j = i - n8x;
        if (j >= n8w) return;
        const float s = scales[(8 * j) >> 7];   // 128-elem blocks; 8-elem chunk never straddles
        const float4* p = reinterpret_cast<const float4*>(wq) + 2 * j;
        float4 a = p[0];
        float4 b = p[1];
        uint4 o;
        o.x = pack2(a.x * s, a.y * s); o.y = pack2(a.z * s, a.w * s);
        o.z = pack2(b.x * s, b.y * s); o.w = pack2(b.z * s, b.w * s);
        reinterpret_cast<uint4*>(g_wh)[j] = o;
    }
}

// ---------------------------------------------------------------------------
// MMA helpers
// ---------------------------------------------------------------------------
__device__ __forceinline__ void cp16(uint32_t saddr, const void* g) {
    asm volatile("cp.async.cg.shared.global [%0], [%1], 16;" ::"r"(saddr), "l"(g));
}
__device__ __forceinline__ void ldsm4(uint32_t* r, uint32_t addr) {
    asm volatile("ldmatrix.sync.aligned.m8n8.x4.shared.b16 {%0,%1,%2,%3}, [%4];"
                 : "=r"(r[0]), "=r"(r[1]), "=r"(r[2]), "=r"(r[3]) : "r"(addr));
}
__device__ __forceinline__ void mma_f16(float* c, const uint32_t* a, const uint32_t* b) {
    asm volatile(
        "mma.sync.aligned.m16n8k16.row.col.f32.f16.f16.f32 "
        "{%0,%1,%2,%3}, {%4,%5,%6,%7}, {%8,%9}, {%0,%1,%2,%3};"
        : "+f"(c[0]), "+f"(c[1]), "+f"(c[2]), "+f"(c[3])
        : "r"(a[0]), "r"(a[1]), "r"(a[2]), "r"(a[3]), "r"(b[0]), "r"(b[1]));
}

// ---------------------------------------------------------------------------
// GEMM: out[M,N] = X16 @ W16^T + bias   (scales pre-folded into W16)
// 4 warps, each 64x64, register fragment double-buffering. (champion, unchanged)
// ---------------------------------------------------------------------------
__global__ __launch_bounds__(THREADS, 2)
void k_gemm(const float* __restrict__ bias, float* __restrict__ out) {
    extern __shared__ char smc[];
    const uint32_t sbase = (uint32_t)__cvta_generic_to_shared(smc);
    const int tid  = threadIdx.x;
    const int lane = tid & 31;
    const int warp = tid >> 5;
    const long m0 = (long)blockIdx.y * BM;
    const long n0 = (long)blockIdx.x * BN;
    const int wm = (warp & 1) * 64;
    const int wn = (warp >> 1) * 64;

    float c[4][8][4];
#pragma unroll
    for (int mi = 0; mi < 4; ++mi)
#pragma unroll
        for (int ni = 0; ni < 8; ++ni)
#pragma unroll
            for (int j = 0; j < 4; ++j) c[mi][ni][j] = 0.f;

    // cp.async loader: 2048 16B-chunks per stage (2 arrays x 1024), 16/thread
    auto load_stage = [&](int kt, int s) {
        const uint32_t st = sbase + s * STG_B;
        const int kc0 = kt * BK;
#pragma unroll
        for (int i = 0; i < 8; ++i) {
            const int cch = tid + i * THREADS;
            const int row = cch >> 3;
            const int ch  = cch & 7;
            const uint32_t off = (uint32_t)(row * ROWB + ch * 16);
            cp16(st + off,         g_xh + (m0 + row) * K_DIM + kc0 + ch * 8);
            cp16(st + ARR_B + off, g_wh + (n0 + row) * (long)K_DIM + kc0 + ch * 8);
        }
        asm volatile("cp.async.commit_group;");
    };

    const int KT = K_DIM / BK;   // 64
    load_stage(0, 0);
    load_stage(1, 1);

    const uint32_t a_rowoff = (uint32_t)(wm + (lane & 15));
    const uint32_t a_cb     = (uint32_t)((lane >> 4) * 16);
    const uint32_t b_rowoff = (uint32_t)(wn + (lane & 7) + ((lane >> 4) * 8));
    const uint32_t b_cb     = (uint32_t)(((lane >> 3) & 1) * 16);

    uint32_t ah[2][4][4], bq[2][4][4];

    auto load_frags = [&](uint32_t st, int kk, int buf) {
#pragma unroll
        for (int mi = 0; mi < 4; ++mi)
            ldsm4(ah[buf][mi], st + (a_rowoff + mi * 16) * ROWB + kk * 32 + a_cb);
#pragma unroll
        for (int nj = 0; nj < 4; ++nj)
            ldsm4(bq[buf][nj], st + ARR_B + (b_rowoff + nj * 16) * ROWB + kk * 32 + b_cb);
    };
    auto do_mmas = [&](int buf) {
#pragma unroll
        for (int mi = 0; mi < 4; ++mi)
#pragma unroll
            for (int nj = 0; nj < 4; ++nj) {
                mma_f16(c[mi][2 * nj],     ah[buf][mi], &bq[buf][nj][0]);
                mma_f16(c[mi][2 * nj + 1], ah[buf][mi], &bq[buf][nj][2]);
            }
    };

    for (int kt = 0; kt < KT; ++kt) {
        const int s = kt % STAGES;
        asm volatile("cp.async.wait_group %0;" :: "n"(STAGES - 2));
        __syncthreads();
        if (kt + 2 < KT) load_stage(kt + 2, (kt + 2) % STAGES);

        const uint32_t st = sbase + s * STG_B;
        load_frags(st, 0, 0);
#pragma unroll
        for (int kk = 0; kk < 4; ++kk) {
            if (kk < 3) load_frags(st, kk + 1, (kk + 1) & 1);
            do_mmas(kk & 1);
        }
    }

    // Epilogue: y += bias, store (each warp: 64 rows x 64 cols)
    const int qr = lane >> 2;
    const int qc = (lane & 3) * 2;
#pragma unroll
    for (int mi = 0; mi < 4; ++mi) {
        const long gm = m0 + wm + mi * 16 + qr;
        float* o0 = out + gm * N_DIM + n0 + wn;
        float* o1 = o0 + 8L * N_DIM;
#pragma unroll
        for (int ni = 0; ni < 8; ++ni) {
            const int col = (int)n0 + wn + ni * 8 + qc;
            const float b0 = __ldg(bias + col);
            const float b1 = __ldg(bias + col + 1);
            float2 v0 = make_float2(c[mi][ni][0] + b0, c[mi][ni][1] + b1);
            float2 v1 = make_float2(c[mi][ni][2] + b0, c[mi][ni][3] + b1);
            *reinterpret_cast<float2*>(o0 + ni * 8 + qc) = v0;
            *reinterpret_cast<float2*>(o1 + ni * 8 + qc) = v1;
        }
    }
}

// ---------------------------------------------------------------------------
// Launch
// ---------------------------------------------------------------------------
extern "C" void kernel_launch(void* const* d_in, const int* in_sizes, int n_in,
                              void* d_out, int out_size) {
    const float* x      = (const float*)d_in[0];
    const float* wq     = (const float*)d_in[1];
    const float* scales = (const float*)d_in[2];
    const float* bias   = (const float*)d_in[3];
    float* out = (float*)d_out;

    const long n_x = in_sizes[0];           // M*K
    const long M   = n_x / K_DIM;           // 8192
    const long n_w = (long)N_DIM * K_DIM;

    const long n8x = n_x / 8;
    const long n8w = n_w / 8;
    const long n8  = n8x + n8w;
    k_prep<<<(int)((n8 + 255) / 256), 256>>>(x, wq, scales, n8x, n8w);

    cudaFuncSetAttribute(k_gemm, cudaFuncAttributeMaxDynamicSharedMemorySize,
                         SMEM_TOTAL);
    dim3 grid(N_DIM / BN, (unsigned)(M / BM));
    k_gemm<<<grid, THREADS, SMEM_TOTAL>>>(bias, out);
}